// round 12
// baseline (speedup 1.0000x reference)
#include <cuda_runtime.h>
#include <cuda_fp16.h>
#include <math.h>

#define B_   128
#define NJ   10
#define NK   1152
#define NM   16
#define NI   8
#define UHR  84          // route smem row pitch in half2 (80 data + 4 pad)
#define CSP  132         // cs row pitch (transposed [j][pair])
#define BT   16          // b per uhat block

// ---------------- scratch (device globals; no allocations) ----------------
__device__ uint2   g_uhat[(size_t)NJ * B_ * 4 * NK];        // [j][b][g][k][m4], 47.2 MB
__device__ float   g_s0part[(size_t)9  * B_ * NJ * NM];     // [kc][pair][m]
__device__ float   g_spart0[(size_t)36 * B_ * NJ * NM];
__device__ float   g_spart1[(size_t)36 * B_ * NJ * NM];
__device__ float   g_w1[B_ * NJ * NM];                      // v0 + v1

// =============== Kernel 1: build u_hat, 16-b tile =========================
__global__ void __launch_bounds__(128) uhat_kernel(const float* __restrict__ x,
                                                   const float* __restrict__ Ws) {
    extern __shared__ float sm[];
    const int kb = blockIdx.x * 128;
    const int j  = blockIdx.y;
    const int b0 = blockIdx.z * BT;
    const int tid = threadIdx.x;

    for (int f = tid; f < 4096; f += 128) {
        int b = f >> 8, r = f & 255;
        int k = r >> 1, q = r & 1;
        float4 v4 = *(const float4*)(x + ((size_t)(b0 + b) * NK + kb + k) * NI + q * 4);
        *(float4*)(sm + (b * 128 + k) * 12 + q * 4) = v4;
    }
    __syncthreads();

    const int p = tid & 31, g = tid >> 5;
    float acc[BT * 4];
#pragma unroll
    for (int t = 0; t < BT * 4; t++) acc[t] = 0.f;

    for (int ki = 0; ki < 4; ki++) {
        const int kl = ki * 32 + p;
        const int k  = kb + kl;
        const float4* wp = (const float4*)(Ws + (((size_t)j * NK + k) * NM + g * 4) * NI);
        float4 w[8];
#pragma unroll
        for (int t = 0; t < 8; t++) w[t] = wp[t];
#pragma unroll
        for (int b = 0; b < BT; b++) {
            const float* xr = sm + (b * 128 + kl) * 12;
            float4 xa = *(const float4*)xr;
            float4 xb = *(const float4*)(xr + 4);
            float4 u;
            u.x = w[0].x*xa.x + w[0].y*xa.y + w[0].z*xa.z + w[0].w*xa.w
                + w[1].x*xb.x + w[1].y*xb.y + w[1].z*xb.z + w[1].w*xb.w;
            u.y = w[2].x*xa.x + w[2].y*xa.y + w[2].z*xa.z + w[2].w*xa.w
                + w[3].x*xb.x + w[3].y*xb.y + w[3].z*xb.z + w[3].w*xb.w;
            u.z = w[4].x*xa.x + w[4].y*xa.y + w[4].z*xa.z + w[4].w*xa.w
                + w[5].x*xb.x + w[5].y*xb.y + w[5].z*xb.z + w[5].w*xb.w;
            u.w = w[6].x*xa.x + w[6].y*xa.y + w[6].z*xa.z + w[6].w*xa.w
                + w[7].x*xb.x + w[7].y*xb.y + w[7].z*xb.z + w[7].w*xb.w;
            __half2 h0 = __float22half2_rn(make_float2(u.x, u.y));
            __half2 h1 = __float22half2_rn(make_float2(u.z, u.w));
            uint2 o;
            o.x = reinterpret_cast<unsigned&>(h0);
            o.y = reinterpret_cast<unsigned&>(h1);
            g_uhat[(((size_t)j * B_ + b0 + b) * 4 + g) * NK + k] = o;
            acc[b * 4 + 0] += u.x;
            acc[b * 4 + 1] += u.y;
            acc[b * 4 + 2] += u.z;
            acc[b * 4 + 3] += u.w;
        }
    }
    __syncthreads();

    float* buf = sm;   // [32 p][257]
#pragma unroll
    for (int b = 0; b < BT; b++)
#pragma unroll
        for (int t = 0; t < 4; t++)
            buf[p * 257 + b * 16 + g * 4 + t] = acc[b * 4 + t];
    __syncthreads();
#pragma unroll
    for (int it = 0; it < 2; it++) {
        const int idx = it * 128 + tid;
        float s = 0.f;
#pragma unroll
        for (int pp = 0; pp < 32; pp++) s += buf[pp * 257 + idx];
        const int bloc = idx >> 4, m = idx & 15;
        g_s0part[(((size_t)blockIdx.x * B_ + (b0 + bloc)) * NJ + j) * NM + m] = s;
    }
}

// =============== Kernel 2: fused routing pass ==============================
// grid (36, 32), block 320. Tile 4b x 32k. cs transposed [j][pair], phase A 256 thr.
template <int ITER>
__global__ void __launch_bounds__(320) route_kernel() {
    extern __shared__ float sm[];
    __half2* uh = (__half2*)sm;            // [128 pairs][UHR half2]
    float* cs = sm + 128 * UHR;            // [10 j][CSP] transposed
    float* ws = cs + NJ * CSP;             // [4][160] routing vector
    const int kb = blockIdx.x * 32;
    const int b0 = blockIdx.y * 4;
    const int tid = threadIdx.x;

    // ---- stream the u_hat tile FIRST (front-batched LDG.128, 256B runs)
#pragma unroll
    for (int it = 0; it < 8; it++) {
        int f = it * 320 + tid;            // 0..2559 uint4
        int kp = f & 15, g = (f >> 4) & 3, bl = (f >> 6) & 3, j = f >> 8;
        uint4 u = *(const uint4*)(g_uhat + ((((size_t)j * B_ + b0 + bl) * 4 + g) * NK + kb + kp * 2));
        const int row = bl * 32 + kp * 2;
        *(uint2*)(uh + row * UHR + j * 8 + g * 2)       = make_uint2(u.x, u.y);
        *(uint2*)(uh + (row + 1) * UHR + j * 8 + g * 2) = make_uint2(u.z, u.w);
    }

    // ---- prologue: routing vector (overlaps with tile-load drain)
    if (ITER == 0) {
        for (int pv = tid; pv < 640; pv += 320) {
            const int bl = pv / 160, r = pv % 160;
            const size_t base = (((size_t)(b0 + bl) * NJ + (r >> 4)) * NM) + (r & 15);
            const size_t stride = (size_t)B_ * NJ * NM;
            float s0 = 0.f;
#pragma unroll
            for (int pp = 0; pp < 9; pp++) s0 += g_s0part[base + pp * stride];
            s0 *= 0.1f;
            float n2 = s0 * s0;
            n2 += __shfl_xor_sync(0xFFFFFFFFu, n2, 1);
            n2 += __shfl_xor_sync(0xFFFFFFFFu, n2, 2);
            n2 += __shfl_xor_sync(0xFFFFFFFFu, n2, 4);
            n2 += __shfl_xor_sync(0xFFFFFFFFu, n2, 8);
            ws[pv] = s0 * (sqrtf(n2) / (1.f + n2));
        }
    } else {
        for (int f = tid; f < 640; f += 320) ws[f] = g_w1[b0 * 160 + f];
    }
    __syncthreads();

    // ---- phase A: logits + softmax; 256 threads = (pair, j-half of 5)
    if (tid < 256) {
        const int pair = tid >> 1, jh = tid & 1;
        const int bl = pair >> 5;
        const uint4* row = (const uint4*)(uh + pair * UHR);
        const float* wr = ws + bl * 160;
        float L[5];
#pragma unroll
        for (int jj = 0; jj < 5; jj++) {
            const int j = jh * 5 + jj;
            uint4 a = row[j * 2];
            uint4 b = row[j * 2 + 1];
            const unsigned int ua[8] = {a.x, a.y, a.z, a.w, b.x, b.y, b.z, b.w};
            float d = 0.f;
#pragma unroll
            for (int q = 0; q < 8; q++) {
                float2 f2 = __half22float2(*(const __half2*)&ua[q]);
                d += f2.x * wr[j * 16 + q * 2] + f2.y * wr[j * 16 + q * 2 + 1];
            }
            L[jj] = d;
        }
        float mx = L[0];
#pragma unroll
        for (int jj = 1; jj < 5; jj++) mx = fmaxf(mx, L[jj]);
        mx = fmaxf(mx, __shfl_xor_sync(0xFFFFFFFFu, mx, 1));
        float e[5], ssum = 0.f;
#pragma unroll
        for (int jj = 0; jj < 5; jj++) { e[jj] = __expf(L[jj] - mx); ssum += e[jj]; }
        ssum += __shfl_xor_sync(0xFFFFFFFFu, ssum, 1);
        const float inv = 1.f / ssum;
#pragma unroll
        for (int jj = 0; jj < 5; jj++) cs[(jh * 5 + jj) * CSP + pair] = e[jj] * inv;
    }
    __syncthreads();

    // ---- phase B: s partials, thread = (bl, j, mh); c loads as LDS.128
    {
        const int bl = tid / 80, r = tid % 80, j = r >> 3, mh = r & 7;
        float2 acc = make_float2(0.f, 0.f);
        const __half2* uhb = uh + (bl * 32) * UHR + j * 8 + mh;
        const float4* c4 = (const float4*)(cs + j * CSP + bl * 32);
#pragma unroll
        for (int q = 0; q < 8; q++) {
            float4 c = c4[q];
            float2 f0 = __half22float2(uhb[(q * 4 + 0) * UHR]);
            float2 f1 = __half22float2(uhb[(q * 4 + 1) * UHR]);
            float2 f2 = __half22float2(uhb[(q * 4 + 2) * UHR]);
            float2 f3 = __half22float2(uhb[(q * 4 + 3) * UHR]);
            acc.x += c.x * f0.x + c.y * f1.x + c.z * f2.x + c.w * f3.x;
            acc.y += c.x * f0.y + c.y * f1.y + c.z * f2.y + c.w * f3.y;
        }
        float* dst = (ITER == 0) ? g_spart0 : g_spart1;
        *(float2*)(dst + ((((size_t)blockIdx.x * B_) + (b0 + bl)) * NJ + j) * NM + mh * 2) = acc;
    }
}

// =============== Kernel 3: w1 = v0 + v1 (warp per pair) ====================
__global__ void compute_w1_kernel() {
    const int warp = (blockIdx.x * blockDim.x + threadIdx.x) >> 5;
    const int lane = threadIdx.x & 31;
    if (warp >= B_ * NJ) return;
    const int q = lane >> 3, t = lane & 7;
    float4 s0 = make_float4(0.f, 0.f, 0.f, 0.f);
    float4 s1 = make_float4(0.f, 0.f, 0.f, 0.f);
#pragma unroll
    for (int p = t; p < 9; p += 8) {
        float4 u = *(const float4*)(g_s0part + ((size_t)p * (B_ * NJ) + warp) * NM + q * 4);
        s0.x += u.x; s0.y += u.y; s0.z += u.z; s0.w += u.w;
    }
#pragma unroll
    for (int p = t; p < 36; p += 8) {
        float4 u = *(const float4*)(g_spart0 + ((size_t)p * (B_ * NJ) + warp) * NM + q * 4);
        s1.x += u.x; s1.y += u.y; s1.z += u.z; s1.w += u.w;
    }
#pragma unroll
    for (int off = 4; off; off >>= 1) {
        s0.x += __shfl_down_sync(0xFFFFFFFFu, s0.x, off);
        s0.y += __shfl_down_sync(0xFFFFFFFFu, s0.y, off);
        s0.z += __shfl_down_sync(0xFFFFFFFFu, s0.z, off);
        s0.w += __shfl_down_sync(0xFFFFFFFFu, s0.w, off);
        s1.x += __shfl_down_sync(0xFFFFFFFFu, s1.x, off);
        s1.y += __shfl_down_sync(0xFFFFFFFFu, s1.y, off);
        s1.z += __shfl_down_sync(0xFFFFFFFFu, s1.z, off);
        s1.w += __shfl_down_sync(0xFFFFFFFFu, s1.w, off);
    }
    s0.x *= 0.1f; s0.y *= 0.1f; s0.z *= 0.1f; s0.w *= 0.1f;
    float a2 = s0.x * s0.x + s0.y * s0.y + s0.z * s0.z + s0.w * s0.w;
    float b2 = s1.x * s1.x + s1.y * s1.y + s1.z * s1.z + s1.w * s1.w;
    float a2t = 0.f, b2t = 0.f;
#pragma unroll
    for (int qq = 0; qq < 4; qq++) {
        a2t += __shfl_sync(0xFFFFFFFFu, a2, qq * 8);
        b2t += __shfl_sync(0xFFFFFFFFu, b2, qq * 8);
    }
    const float fa = sqrtf(a2t) / (1.f + a2t);
    const float fb = sqrtf(b2t) / (1.f + b2t);
    if (t == 0) {
        float4 o = make_float4(s0.x * fa + s1.x * fb, s0.y * fa + s1.y * fb,
                               s0.z * fa + s1.z * fb, s0.w * fa + s1.w * fb);
        *(float4*)(g_w1 + warp * NM + q * 4) = o;
    }
}

// =============== Kernel 4: final reduce + squash (warp per pair) ===========
__global__ void squash_final(float* __restrict__ out) {
    const int warp = (blockIdx.x * blockDim.x + threadIdx.x) >> 5;
    const int lane = threadIdx.x & 31;
    if (warp >= B_ * NJ) return;
    const int q = lane >> 3, t = lane & 7;
    float4 s = make_float4(0.f, 0.f, 0.f, 0.f);
#pragma unroll
    for (int p = t; p < 36; p += 8) {
        float4 u = *(const float4*)(g_spart1 + ((size_t)p * (B_ * NJ) + warp) * NM + q * 4);
        s.x += u.x; s.y += u.y; s.z += u.z; s.w += u.w;
    }
#pragma unroll
    for (int off = 4; off; off >>= 1) {
        s.x += __shfl_down_sync(0xFFFFFFFFu, s.x, off);
        s.y += __shfl_down_sync(0xFFFFFFFFu, s.y, off);
        s.z += __shfl_down_sync(0xFFFFFFFFu, s.z, off);
        s.w += __shfl_down_sync(0xFFFFFFFFu, s.w, off);
    }
    float n2 = s.x * s.x + s.y * s.y + s.z * s.z + s.w * s.w;
    float n2tot = 0.f;
#pragma unroll
    for (int qq = 0; qq < 4; qq++) n2tot += __shfl_sync(0xFFFFFFFFu, n2, qq * 8);
    const float f = sqrtf(n2tot) / (1.f + n2tot);
    if (t == 0)
        *(float4*)(out + warp * NM + q * 4) = make_float4(s.x * f, s.y * f, s.z * f, s.w * f);
}

// ---------------------------------------------------------------------------
extern "C" void kernel_launch(void* const* d_in, const int* in_sizes, int n_in,
                              void* d_out, int out_size) {
    const float* x  = (const float*)d_in[0];
    const float* Ws = (const float*)d_in[1];
    if (n_in >= 2 && in_sizes[0] == NJ * NK * NM * NI) { const float* t = x; x = Ws; Ws = t; }
    float* out = (float*)d_out;

    const int SMEM_U = BT * 128 * 12 * 4;                            // 98,304 B
    const int SMEM_R = (128 * UHR + NJ * CSP + 640) * 4;             // 50,928 B
    cudaFuncSetAttribute(uhat_kernel,     cudaFuncAttributeMaxDynamicSharedMemorySize, SMEM_U);
    cudaFuncSetAttribute(route_kernel<0>, cudaFuncAttributeMaxDynamicSharedMemorySize, SMEM_R);
    cudaFuncSetAttribute(route_kernel<1>, cudaFuncAttributeMaxDynamicSharedMemorySize, SMEM_R);

    uhat_kernel<<<dim3(9, 10, 8), 128, SMEM_U>>>(x, Ws);
    route_kernel<0><<<dim3(36, 32), 320, SMEM_R>>>();
    compute_w1_kernel<<<160, 256>>>();
    route_kernel<1><<<dim3(36, 32), 320, SMEM_R>>>();
    squash_final<<<160, 256>>>(out);
}

// round 13
// speedup vs baseline: 1.0180x; 1.0180x over previous
#include <cuda_runtime.h>
#include <cuda_fp16.h>
#include <math.h>

#define B_   128
#define NJ   10
#define NK   1152
#define NM   16
#define NI   8
#define UHR  84          // route smem row pitch in half2 (80 data + 4 pad)
#define BT   16          // b per uhat block

// ---------------- scratch (device globals; no allocations) ----------------
__device__ uint2   g_uhat[(size_t)NJ * B_ * 4 * NK];        // [j][b][g][k][m4], 47.2 MB
__device__ float   g_s0part[(size_t)9  * B_ * NJ * NM];     // [kc][pair][m]
__device__ float   g_spart0[(size_t)36 * B_ * NJ * NM];
__device__ float   g_spart1[(size_t)36 * B_ * NJ * NM];
__device__ float   g_w1[B_ * NJ * NM];                      // v0 + v1

// =============== Kernel 1: build u_hat, 16-b tile ==========================
__global__ void __launch_bounds__(128) uhat_kernel(const float* __restrict__ x,
                                                   const float* __restrict__ Ws) {
    extern __shared__ float sm[];
    const int kb = blockIdx.x * 128;
    const int j  = blockIdx.y;
    const int b0 = blockIdx.z * BT;
    const int tid = threadIdx.x;

    for (int f = tid; f < 4096; f += 128) {
        int b = f >> 8, r = f & 255;
        int k = r >> 1, q = r & 1;
        float4 v4 = *(const float4*)(x + ((size_t)(b0 + b) * NK + kb + k) * NI + q * 4);
        *(float4*)(sm + (b * 128 + k) * 12 + q * 4) = v4;
    }
    __syncthreads();
    cudaTriggerProgrammaticLaunchCompletion();

    const int p = tid & 31, g = tid >> 5;
    float acc[BT * 4];
#pragma unroll
    for (int t = 0; t < BT * 4; t++) acc[t] = 0.f;

    for (int ki = 0; ki < 4; ki++) {
        const int kl = ki * 32 + p;
        const int k  = kb + kl;
        const float4* wp = (const float4*)(Ws + (((size_t)j * NK + k) * NM + g * 4) * NI);
        float4 w[8];
#pragma unroll
        for (int t = 0; t < 8; t++) w[t] = wp[t];
#pragma unroll
        for (int b = 0; b < BT; b++) {
            const float* xr = sm + (b * 128 + kl) * 12;
            float4 xa = *(const float4*)xr;
            float4 xb = *(const float4*)(xr + 4);
            float4 u;
            u.x = w[0].x*xa.x + w[0].y*xa.y + w[0].z*xa.z + w[0].w*xa.w
                + w[1].x*xb.x + w[1].y*xb.y + w[1].z*xb.z + w[1].w*xb.w;
            u.y = w[2].x*xa.x + w[2].y*xa.y + w[2].z*xa.z + w[2].w*xa.w
                + w[3].x*xb.x + w[3].y*xb.y + w[3].z*xb.z + w[3].w*xb.w;
            u.z = w[4].x*xa.x + w[4].y*xa.y + w[4].z*xa.z + w[4].w*xa.w
                + w[5].x*xb.x + w[5].y*xb.y + w[5].z*xb.z + w[5].w*xb.w;
            u.w = w[6].x*xa.x + w[6].y*xa.y + w[6].z*xa.z + w[6].w*xa.w
                + w[7].x*xb.x + w[7].y*xb.y + w[7].z*xb.z + w[7].w*xb.w;
            __half2 h0 = __float22half2_rn(make_float2(u.x, u.y));
            __half2 h1 = __float22half2_rn(make_float2(u.z, u.w));
            uint2 o;
            o.x = reinterpret_cast<unsigned&>(h0);
            o.y = reinterpret_cast<unsigned&>(h1);
            g_uhat[(((size_t)j * B_ + b0 + b) * 4 + g) * NK + k] = o;   // 256B run/warp
            acc[b * 4 + 0] += u.x;
            acc[b * 4 + 1] += u.y;
            acc[b * 4 + 2] += u.z;
            acc[b * 4 + 3] += u.w;
        }
    }
    __syncthreads();

    float* buf = sm;   // [32 p][257]
#pragma unroll
    for (int b = 0; b < BT; b++)
#pragma unroll
        for (int t = 0; t < 4; t++)
            buf[p * 257 + b * 16 + g * 4 + t] = acc[b * 4 + t];
    __syncthreads();
#pragma unroll
    for (int it = 0; it < 2; it++) {
        const int idx = it * 128 + tid;
        float s = 0.f;
#pragma unroll
        for (int pp = 0; pp < 32; pp++) s += buf[pp * 257 + idx];
        const int bloc = idx >> 4, m = idx & 15;
        g_s0part[(((size_t)blockIdx.x * B_ + (b0 + bloc)) * NJ + j) * NM + m] = s;
    }
}

// =============== Kernel 2: fused routing pass ==============================
// ITER 0: w = v0 computed inline from g_s0part; ITER 1: w = g_w1.
template <int ITER>
__global__ void __launch_bounds__(320) route_kernel() {
    extern __shared__ float sm[];
    __half2* uh = (__half2*)sm;            // [128 pairs][UHR half2]
    float* cs = sm + 128 * UHR;            // [128][10]
    float* ws = cs + 1280;                 // [4][160] routing vector
    const int kb = blockIdx.x * 32;
    const int b0 = blockIdx.y * 4;
    const int tid = threadIdx.x;

    cudaGridDependencySynchronize();       // wait for predecessor data (PDL)
    cudaTriggerProgrammaticLaunchCompletion();

    // ---- stream the u_hat tile FIRST (front-batched LDG.128, 256B runs)
#pragma unroll
    for (int it = 0; it < 8; it++) {
        int f = it * 320 + tid;            // 0..2559 uint4
        int kp = f & 15, g = (f >> 4) & 3, bl = (f >> 6) & 3, j = f >> 8;
        uint4 u = *(const uint4*)(g_uhat + ((((size_t)j * B_ + b0 + bl) * 4 + g) * NK + kb + kp * 2));
        const int row = bl * 32 + kp * 2;
        *(uint2*)(uh + row * UHR + j * 8 + g * 2)       = make_uint2(u.x, u.y);
        *(uint2*)(uh + (row + 1) * UHR + j * 8 + g * 2) = make_uint2(u.z, u.w);
    }

    // ---- prologue: routing vector (overlaps with tile-load drain)
    if (ITER == 0) {
        for (int pv = tid; pv < 640; pv += 320) {
            const int bl = pv / 160, r = pv % 160;
            const size_t base = (((size_t)(b0 + bl) * NJ + (r >> 4)) * NM) + (r & 15);
            const size_t stride = (size_t)B_ * NJ * NM;
            float s0 = 0.f;
#pragma unroll
            for (int pp = 0; pp < 9; pp++) s0 += g_s0part[base + pp * stride];
            s0 *= 0.1f;
            float n2 = s0 * s0;
            n2 += __shfl_xor_sync(0xFFFFFFFFu, n2, 1);
            n2 += __shfl_xor_sync(0xFFFFFFFFu, n2, 2);
            n2 += __shfl_xor_sync(0xFFFFFFFFu, n2, 4);
            n2 += __shfl_xor_sync(0xFFFFFFFFu, n2, 8);
            ws[pv] = s0 * (sqrtf(n2) / (1.f + n2));
        }
    } else {
        for (int f = tid; f < 640; f += 320) ws[f] = g_w1[b0 * 160 + f];
    }
    __syncthreads();

    // ---- phase A: logits + softmax, one thread per (b,k); LDS.128 reads
    if (tid < 128) {
        const int bl = tid >> 5;
        const uint4* row = (const uint4*)(uh + tid * UHR);
        const float* wr = ws + bl * 160;
        float L[10];
#pragma unroll
        for (int j = 0; j < 10; j++) {
            uint4 a = row[j * 2];
            uint4 b = row[j * 2 + 1];
            const unsigned int ua[8] = {a.x, a.y, a.z, a.w, b.x, b.y, b.z, b.w};
            float d = 0.f;
#pragma unroll
            for (int q = 0; q < 8; q++) {
                float2 f2 = __half22float2(*(const __half2*)&ua[q]);
                d += f2.x * wr[j * 16 + q * 2] + f2.y * wr[j * 16 + q * 2 + 1];
            }
            L[j] = d;
        }
        float mx = L[0];
#pragma unroll
        for (int j = 1; j < 10; j++) mx = fmaxf(mx, L[j]);
        float e[10], ssum = 0.f;
#pragma unroll
        for (int j = 0; j < 10; j++) { e[j] = __expf(L[j] - mx); ssum += e[j]; }
        const float inv = 1.f / ssum;
#pragma unroll
        for (int j = 0; j < 10; j++) cs[tid * 10 + j] = e[j] * inv;
    }
    __syncthreads();

    // ---- phase B: s partials, thread = (bl, j, mh): 4*10*8 = 320
    {
        const int bl = tid / 80, r = tid % 80, j = r >> 3, mh = r & 7;
        float2 acc = make_float2(0.f, 0.f);
        const __half2* uhb = uh + (bl * 32) * UHR + j * 8 + mh;
        const float* csb = cs + (bl * 32) * 10 + j;
#pragma unroll
        for (int kl = 0; kl < 32; kl++) {
            float c = csb[kl * 10];
            float2 f2 = __half22float2(uhb[kl * UHR]);
            acc.x += c * f2.x; acc.y += c * f2.y;
        }
        float* dst = (ITER == 0) ? g_spart0 : g_spart1;
        *(float2*)(dst + ((((size_t)blockIdx.x * B_) + (b0 + bl)) * NJ + j) * NM + mh * 2) = acc;
    }
}

// =============== Kernel 3: w1 = v0 + v1 (warp per pair) ====================
__global__ void compute_w1_kernel() {
    cudaGridDependencySynchronize();
    cudaTriggerProgrammaticLaunchCompletion();
    const int warp = (blockIdx.x * blockDim.x + threadIdx.x) >> 5;
    const int lane = threadIdx.x & 31;
    if (warp >= B_ * NJ) return;
    const int q = lane >> 3, t = lane & 7;
    float4 s0 = make_float4(0.f, 0.f, 0.f, 0.f);
    float4 s1 = make_float4(0.f, 0.f, 0.f, 0.f);
#pragma unroll
    for (int p = t; p < 9; p += 8) {
        float4 u = *(const float4*)(g_s0part + ((size_t)p * (B_ * NJ) + warp) * NM + q * 4);
        s0.x += u.x; s0.y += u.y; s0.z += u.z; s0.w += u.w;
    }
#pragma unroll
    for (int p = t; p < 36; p += 8) {
        float4 u = *(const float4*)(g_spart0 + ((size_t)p * (B_ * NJ) + warp) * NM + q * 4);
        s1.x += u.x; s1.y += u.y; s1.z += u.z; s1.w += u.w;
    }
#pragma unroll
    for (int off = 4; off; off >>= 1) {
        s0.x += __shfl_down_sync(0xFFFFFFFFu, s0.x, off);
        s0.y += __shfl_down_sync(0xFFFFFFFFu, s0.y, off);
        s0.z += __shfl_down_sync(0xFFFFFFFFu, s0.z, off);
        s0.w += __shfl_down_sync(0xFFFFFFFFu, s0.w, off);
        s1.x += __shfl_down_sync(0xFFFFFFFFu, s1.x, off);
        s1.y += __shfl_down_sync(0xFFFFFFFFu, s1.y, off);
        s1.z += __shfl_down_sync(0xFFFFFFFFu, s1.z, off);
        s1.w += __shfl_down_sync(0xFFFFFFFFu, s1.w, off);
    }
    s0.x *= 0.1f; s0.y *= 0.1f; s0.z *= 0.1f; s0.w *= 0.1f;
    float a2 = s0.x * s0.x + s0.y * s0.y + s0.z * s0.z + s0.w * s0.w;
    float b2 = s1.x * s1.x + s1.y * s1.y + s1.z * s1.z + s1.w * s1.w;
    float a2t = 0.f, b2t = 0.f;
#pragma unroll
    for (int qq = 0; qq < 4; qq++) {
        a2t += __shfl_sync(0xFFFFFFFFu, a2, qq * 8);
        b2t += __shfl_sync(0xFFFFFFFFu, b2, qq * 8);
    }
    const float fa = sqrtf(a2t) / (1.f + a2t);
    const float fb = sqrtf(b2t) / (1.f + b2t);
    if (t == 0) {
        float4 o = make_float4(s0.x * fa + s1.x * fb, s0.y * fa + s1.y * fb,
                               s0.z * fa + s1.z * fb, s0.w * fa + s1.w * fb);
        *(float4*)(g_w1 + warp * NM + q * 4) = o;
    }
}

// =============== Kernel 4: final reduce + squash (warp per pair) ===========
__global__ void squash_final(float* __restrict__ out) {
    cudaGridDependencySynchronize();
    const int warp = (blockIdx.x * blockDim.x + threadIdx.x) >> 5;
    const int lane = threadIdx.x & 31;
    if (warp >= B_ * NJ) return;
    const int q = lane >> 3, t = lane & 7;
    float4 s = make_float4(0.f, 0.f, 0.f, 0.f);
#pragma unroll
    for (int p = t; p < 36; p += 8) {
        float4 u = *(const float4*)(g_spart1 + ((size_t)p * (B_ * NJ) + warp) * NM + q * 4);
        s.x += u.x; s.y += u.y; s.z += u.z; s.w += u.w;
    }
#pragma unroll
    for (int off = 4; off; off >>= 1) {
        s.x += __shfl_down_sync(0xFFFFFFFFu, s.x, off);
        s.y += __shfl_down_sync(0xFFFFFFFFu, s.y, off);
        s.z += __shfl_down_sync(0xFFFFFFFFu, s.z, off);
        s.w += __shfl_down_sync(0xFFFFFFFFu, s.w, off);
    }
    float n2 = s.x * s.x + s.y * s.y + s.z * s.z + s.w * s.w;
    float n2tot = 0.f;
#pragma unroll
    for (int qq = 0; qq < 4; qq++) n2tot += __shfl_sync(0xFFFFFFFFu, n2, qq * 8);
    const float f = sqrtf(n2tot) / (1.f + n2tot);
    if (t == 0)
        *(float4*)(out + warp * NM + q * 4) = make_float4(s.x * f, s.y * f, s.z * f, s.w * f);
}

// ---------------------------------------------------------------------------
template <typename K, typename... Args>
static void launch_pdl(K kernel, dim3 grid, dim3 block, size_t smem, Args... args) {
    cudaLaunchConfig_t cfg = {};
    cfg.gridDim = grid;
    cfg.blockDim = block;
    cfg.dynamicSmemBytes = smem;
    cudaLaunchAttribute attr[1];
    attr[0].id = cudaLaunchAttributeProgrammaticStreamSerialization;
    attr[0].val.programmaticStreamSerializationAllowed = 1;
    cfg.attrs = attr;
    cfg.numAttrs = 1;
    cudaLaunchKernelEx(&cfg, kernel, args...);
}

extern "C" void kernel_launch(void* const* d_in, const int* in_sizes, int n_in,
                              void* d_out, int out_size) {
    const float* x  = (const float*)d_in[0];
    const float* Ws = (const float*)d_in[1];
    if (n_in >= 2 && in_sizes[0] == NJ * NK * NM * NI) { const float* t = x; x = Ws; Ws = t; }
    float* out = (float*)d_out;

    const int SMEM_U = BT * 128 * 12 * 4;                            // 98,304 B
    const int SMEM_R = (128 * UHR + 1280 + 640) * 4;                 // 50,688 B
    cudaFuncSetAttribute(uhat_kernel,     cudaFuncAttributeMaxDynamicSharedMemorySize, SMEM_U);
    cudaFuncSetAttribute(route_kernel<0>, cudaFuncAttributeMaxDynamicSharedMemorySize, SMEM_R);
    cudaFuncSetAttribute(route_kernel<1>, cudaFuncAttributeMaxDynamicSharedMemorySize, SMEM_R);

    // 1) u_hat (fp16) + s0 partials
    uhat_kernel<<<dim3(9, 10, 8), 128, SMEM_U>>>(x, Ws);
    // 2..5) PDL-chained: each successor's ramp overlaps predecessor's tail
    launch_pdl(route_kernel<0>,  dim3(36, 32), dim3(320), SMEM_R);
    launch_pdl(compute_w1_kernel, dim3(160),    dim3(256), 0);
    launch_pdl(route_kernel<1>,  dim3(36, 32), dim3(320), SMEM_R);
    launch_pdl(squash_final,     dim3(160),    dim3(256), 0, out);
}

// round 14
// speedup vs baseline: 1.0214x; 1.0034x over previous
#include <cuda_runtime.h>
#include <cuda_fp16.h>
#include <math.h>

#define B_   128
#define NJ   10
#define NK   1152
#define NM   16
#define NI   8
#define UHR  84          // route smem row pitch in half2 (80 data + 4 pad, 16B-aligned rows)
#define BT   16          // b per uhat block

// ---------------- scratch (device globals; no allocations) ----------------
__device__ uint2   g_uhat[(size_t)NJ * B_ * 4 * NK];        // [j][b][g][k][m4], 47.2 MB
__device__ float   g_s0part[(size_t)9  * B_ * NJ * NM];     // [kc][pair][m]
__device__ float   g_spart0[(size_t)36 * B_ * NJ * NM];
__device__ float   g_spart1[(size_t)36 * B_ * NJ * NM];
__device__ float   g_w1[B_ * NJ * NM];                      // v0 + v1

// =============== Kernel 1: build u_hat, 16-b tile ==========================
__global__ void __launch_bounds__(128) uhat_kernel(const float* __restrict__ x,
                                                   const float* __restrict__ Ws) {
    extern __shared__ float sm[];
    const int kb = blockIdx.x * 128;
    const int j  = blockIdx.y;
    const int b0 = blockIdx.z * BT;
    const int tid = threadIdx.x;

    for (int f = tid; f < 4096; f += 128) {
        int b = f >> 8, r = f & 255;
        int k = r >> 1, q = r & 1;
        float4 v4 = *(const float4*)(x + ((size_t)(b0 + b) * NK + kb + k) * NI + q * 4);
        *(float4*)(sm + (b * 128 + k) * 12 + q * 4) = v4;
    }
    __syncthreads();
    cudaTriggerProgrammaticLaunchCompletion();

    const int p = tid & 31, g = tid >> 5;
    float acc[BT * 4];
#pragma unroll
    for (int t = 0; t < BT * 4; t++) acc[t] = 0.f;

    for (int ki = 0; ki < 4; ki++) {
        const int kl = ki * 32 + p;
        const int k  = kb + kl;
        const float4* wp = (const float4*)(Ws + (((size_t)j * NK + k) * NM + g * 4) * NI);
        float4 w[8];
#pragma unroll
        for (int t = 0; t < 8; t++) w[t] = wp[t];
#pragma unroll
        for (int b = 0; b < BT; b++) {
            const float* xr = sm + (b * 128 + kl) * 12;
            float4 xa = *(const float4*)xr;
            float4 xb = *(const float4*)(xr + 4);
            float4 u;
            u.x = w[0].x*xa.x + w[0].y*xa.y + w[0].z*xa.z + w[0].w*xa.w
                + w[1].x*xb.x + w[1].y*xb.y + w[1].z*xb.z + w[1].w*xb.w;
            u.y = w[2].x*xa.x + w[2].y*xa.y + w[2].z*xa.z + w[2].w*xa.w
                + w[3].x*xb.x + w[3].y*xb.y + w[3].z*xb.z + w[3].w*xb.w;
            u.z = w[4].x*xa.x + w[4].y*xa.y + w[4].z*xa.z + w[4].w*xa.w
                + w[5].x*xb.x + w[5].y*xb.y + w[5].z*xb.z + w[5].w*xb.w;
            u.w = w[6].x*xa.x + w[6].y*xa.y + w[6].z*xa.z + w[6].w*xa.w
                + w[7].x*xb.x + w[7].y*xb.y + w[7].z*xb.z + w[7].w*xb.w;
            __half2 h0 = __float22half2_rn(make_float2(u.x, u.y));
            __half2 h1 = __float22half2_rn(make_float2(u.z, u.w));
            uint2 o;
            o.x = reinterpret_cast<unsigned&>(h0);
            o.y = reinterpret_cast<unsigned&>(h1);
            g_uhat[(((size_t)j * B_ + b0 + b) * 4 + g) * NK + k] = o;
            acc[b * 4 + 0] += u.x;
            acc[b * 4 + 1] += u.y;
            acc[b * 4 + 2] += u.z;
            acc[b * 4 + 3] += u.w;
        }
    }
    __syncthreads();

    float* buf = sm;   // [32 p][257]
#pragma unroll
    for (int b = 0; b < BT; b++)
#pragma unroll
        for (int t = 0; t < 4; t++)
            buf[p * 257 + b * 16 + g * 4 + t] = acc[b * 4 + t];
    __syncthreads();
#pragma unroll
    for (int it = 0; it < 2; it++) {
        const int idx = it * 128 + tid;
        float s = 0.f;
#pragma unroll
        for (int pp = 0; pp < 32; pp++) s += buf[pp * 257 + idx];
        const int bloc = idx >> 4, m = idx & 15;
        g_s0part[(((size_t)blockIdx.x * B_ + (b0 + bloc)) * NJ + j) * NM + m] = s;
    }
}

// =============== Kernel 2: fused routing pass (2b x 32k tile) ==============
// grid (36, 64), block 160, smem 25.3KB -> 9 CTA/SM.
template <int ITER>
__global__ void __launch_bounds__(160) route_kernel() {
    extern __shared__ float sm[];
    __half2* uh = (__half2*)sm;            // [64 pairs][UHR half2]
    float* cs = sm + 64 * UHR;             // [64][10]
    float* ws = cs + 640;                  // [2][160]; reused as kh-exchange in phase B
    const int kb = blockIdx.x * 32;
    const int b0 = blockIdx.y * 2;
    const int tid = threadIdx.x;

    cudaGridDependencySynchronize();
    cudaTriggerProgrammaticLaunchCompletion();

    // ---- stream the u_hat tile FIRST (1280 uint4, front-batched)
#pragma unroll
    for (int it = 0; it < 8; it++) {
        int f = it * 160 + tid;            // 0..1279
        int kp = f & 15, g = (f >> 4) & 3, bl = (f >> 6) & 1, j = f >> 7;
        uint4 u = *(const uint4*)(g_uhat + ((((size_t)j * B_ + b0 + bl) * 4 + g) * NK + kb + kp * 2));
        const int row = bl * 32 + kp * 2;
        *(uint2*)(uh + row * UHR + j * 8 + g * 2)       = make_uint2(u.x, u.y);
        *(uint2*)(uh + (row + 1) * UHR + j * 8 + g * 2) = make_uint2(u.z, u.w);
    }

    // ---- prologue: routing vector (320 floats, overlaps tile-load drain)
    if (ITER == 0) {
#pragma unroll
        for (int pv = tid; pv < 320; pv += 160) {
            const int bl = pv / 160, r = pv % 160;
            const size_t base = (((size_t)(b0 + bl) * NJ + (r >> 4)) * NM) + (r & 15);
            const size_t stride = (size_t)B_ * NJ * NM;
            float s0 = 0.f;
#pragma unroll
            for (int pp = 0; pp < 9; pp++) s0 += g_s0part[base + pp * stride];
            s0 *= 0.1f;
            float n2 = s0 * s0;
            n2 += __shfl_xor_sync(0xFFFFFFFFu, n2, 1);
            n2 += __shfl_xor_sync(0xFFFFFFFFu, n2, 2);
            n2 += __shfl_xor_sync(0xFFFFFFFFu, n2, 4);
            n2 += __shfl_xor_sync(0xFFFFFFFFu, n2, 8);
            ws[pv] = s0 * (sqrtf(n2) / (1.f + n2));
        }
    } else {
#pragma unroll
        for (int f = tid; f < 320; f += 160) ws[f] = g_w1[b0 * 160 + f];
    }
    __syncthreads();

    // ---- phase A: logits + softmax; 128 threads = (pair, j-half of 5)
    if (tid < 128) {
        const int pair = tid >> 1, jh = tid & 1;
        const int bl = pair >> 5;
        const uint4* row = (const uint4*)(uh + pair * UHR);
        const float* wr = ws + bl * 160;
        float L[5];
#pragma unroll
        for (int jj = 0; jj < 5; jj++) {
            const int j = jh * 5 + jj;
            uint4 a = row[j * 2];
            uint4 b = row[j * 2 + 1];
            const unsigned int ua[8] = {a.x, a.y, a.z, a.w, b.x, b.y, b.z, b.w};
            float d = 0.f;
#pragma unroll
            for (int q = 0; q < 8; q++) {
                float2 f2 = __half22float2(*(const __half2*)&ua[q]);
                d += f2.x * wr[j * 16 + q * 2] + f2.y * wr[j * 16 + q * 2 + 1];
            }
            L[jj] = d;
        }
        float mx = L[0];
#pragma unroll
        for (int jj = 1; jj < 5; jj++) mx = fmaxf(mx, L[jj]);
        mx = fmaxf(mx, __shfl_xor_sync(0xFFFFFFFFu, mx, 1));
        float e[5], ssum = 0.f;
#pragma unroll
        for (int jj = 0; jj < 5; jj++) { e[jj] = __expf(L[jj] - mx); ssum += e[jj]; }
        ssum += __shfl_xor_sync(0xFFFFFFFFu, ssum, 1);
        const float inv = 1.f / ssum;
#pragma unroll
        for (int jj = 0; jj < 5; jj++) cs[pair * 10 + jh * 5 + jj] = e[jj] * inv;
    }
    __syncthreads();

    // ---- phase B: split-k s partials. thread = (kh, bl, j, mq): 2*2*10*4 = 160
    {
        const int kh = tid / 80, r = tid % 80;
        const int bl = r / 40, rr = r % 40, j = rr >> 2, mq = rr & 3;
        float4 acc = make_float4(0.f, 0.f, 0.f, 0.f);
        const __half2* uhb = uh + (bl * 32 + kh * 16) * UHR + j * 8 + mq * 2;
        const float* csb = cs + (bl * 32 + kh * 16) * 10 + j;
#pragma unroll
        for (int i = 0; i < 16; i++) {
            float c = csb[i * 10];
            uint2 uu = *(const uint2*)(uhb + i * UHR);          // LDS.64: m-quad
            float2 f0 = __half22float2(*(const __half2*)&uu.x);
            float2 f1 = __half22float2(*(const __half2*)&uu.y);
            acc.x += c * f0.x; acc.y += c * f0.y;
            acc.z += c * f1.x; acc.w += c * f1.y;
        }
        // kh=1 stores partial to exchange buffer (reuses ws region: 80 float4 = 320 floats)
        if (kh == 1) *(float4*)(ws + r * 4) = acc;
        __syncthreads();
        if (kh == 0) {
            float4 o = *(const float4*)(ws + r * 4);
            acc.x += o.x; acc.y += o.y; acc.z += o.z; acc.w += o.w;
            float* dst = (ITER == 0) ? g_spart0 : g_spart1;
            *(float4*)(dst + ((((size_t)blockIdx.x * B_) + (b0 + bl)) * NJ + j) * NM + mq * 4) = acc;
        }
    }
}

// =============== Kernel 3: w1 = v0 + v1 (warp per pair) ====================
__global__ void compute_w1_kernel() {
    cudaGridDependencySynchronize();
    cudaTriggerProgrammaticLaunchCompletion();
    const int warp = (blockIdx.x * blockDim.x + threadIdx.x) >> 5;
    const int lane = threadIdx.x & 31;
    if (warp >= B_ * NJ) return;
    const int q = lane >> 3, t = lane & 7;
    float4 s0 = make_float4(0.f, 0.f, 0.f, 0.f);
    float4 s1 = make_float4(0.f, 0.f, 0.f, 0.f);
#pragma unroll
    for (int p = t; p < 9; p += 8) {
        float4 u = *(const float4*)(g_s0part + ((size_t)p * (B_ * NJ) + warp) * NM + q * 4);
        s0.x += u.x; s0.y += u.y; s0.z += u.z; s0.w += u.w;
    }
#pragma unroll
    for (int p = t; p < 36; p += 8) {
        float4 u = *(const float4*)(g_spart0 + ((size_t)p * (B_ * NJ) + warp) * NM + q * 4);
        s1.x += u.x; s1.y += u.y; s1.z += u.z; s1.w += u.w;
    }
#pragma unroll
    for (int off = 4; off; off >>= 1) {
        s0.x += __shfl_down_sync(0xFFFFFFFFu, s0.x, off);
        s0.y += __shfl_down_sync(0xFFFFFFFFu, s0.y, off);
        s0.z += __shfl_down_sync(0xFFFFFFFFu, s0.z, off);
        s0.w += __shfl_down_sync(0xFFFFFFFFu, s0.w, off);
        s1.x += __shfl_down_sync(0xFFFFFFFFu, s1.x, off);
        s1.y += __shfl_down_sync(0xFFFFFFFFu, s1.y, off);
        s1.z += __shfl_down_sync(0xFFFFFFFFu, s1.z, off);
        s1.w += __shfl_down_sync(0xFFFFFFFFu, s1.w, off);
    }
    s0.x *= 0.1f; s0.y *= 0.1f; s0.z *= 0.1f; s0.w *= 0.1f;
    float a2 = s0.x * s0.x + s0.y * s0.y + s0.z * s0.z + s0.w * s0.w;
    float b2 = s1.x * s1.x + s1.y * s1.y + s1.z * s1.z + s1.w * s1.w;
    float a2t = 0.f, b2t = 0.f;
#pragma unroll
    for (int qq = 0; qq < 4; qq++) {
        a2t += __shfl_sync(0xFFFFFFFFu, a2, qq * 8);
        b2t += __shfl_sync(0xFFFFFFFFu, b2, qq * 8);
    }
    const float fa = sqrtf(a2t) / (1.f + a2t);
    const float fb = sqrtf(b2t) / (1.f + b2t);
    if (t == 0) {
        float4 o = make_float4(s0.x * fa + s1.x * fb, s0.y * fa + s1.y * fb,
                               s0.z * fa + s1.z * fb, s0.w * fa + s1.w * fb);
        *(float4*)(g_w1 + warp * NM + q * 4) = o;
    }
}

// =============== Kernel 4: final reduce + squash (warp per pair) ===========
__global__ void squash_final(float* __restrict__ out) {
    cudaGridDependencySynchronize();
    const int warp = (blockIdx.x * blockDim.x + threadIdx.x) >> 5;
    const int lane = threadIdx.x & 31;
    if (warp >= B_ * NJ) return;
    const int q = lane >> 3, t = lane & 7;
    float4 s = make_float4(0.f, 0.f, 0.f, 0.f);
#pragma unroll
    for (int p = t; p < 36; p += 8) {
        float4 u = *(const float4*)(g_spart1 + ((size_t)p * (B_ * NJ) + warp) * NM + q * 4);
        s.x += u.x; s.y += u.y; s.z += u.z; s.w += u.w;
    }
#pragma unroll
    for (int off = 4; off; off >>= 1) {
        s.x += __shfl_down_sync(0xFFFFFFFFu, s.x, off);
        s.y += __shfl_down_sync(0xFFFFFFFFu, s.y, off);
        s.z += __shfl_down_sync(0xFFFFFFFFu, s.z, off);
        s.w += __shfl_down_sync(0xFFFFFFFFu, s.w, off);
    }
    float n2 = s.x * s.x + s.y * s.y + s.z * s.z + s.w * s.w;
    float n2tot = 0.f;
#pragma unroll
    for (int qq = 0; qq < 4; qq++) n2tot += __shfl_sync(0xFFFFFFFFu, n2, qq * 8);
    const float f = sqrtf(n2tot) / (1.f + n2tot);
    if (t == 0)
        *(float4*)(out + warp * NM + q * 4) = make_float4(s.x * f, s.y * f, s.z * f, s.w * f);
}

// ---------------------------------------------------------------------------
template <typename K, typename... Args>
static void launch_pdl(K kernel, dim3 grid, dim3 block, size_t smem, Args... args) {
    cudaLaunchConfig_t cfg = {};
    cfg.gridDim = grid;
    cfg.blockDim = block;
    cfg.dynamicSmemBytes = smem;
    cudaLaunchAttribute attr[1];
    attr[0].id = cudaLaunchAttributeProgrammaticStreamSerialization;
    attr[0].val.programmaticStreamSerializationAllowed = 1;
    cfg.attrs = attr;
    cfg.numAttrs = 1;
    cudaLaunchKernelEx(&cfg, kernel, args...);
}

extern "C" void kernel_launch(void* const* d_in, const int* in_sizes, int n_in,
                              void* d_out, int out_size) {
    const float* x  = (const float*)d_in[0];
    const float* Ws = (const float*)d_in[1];
    if (n_in >= 2 && in_sizes[0] == NJ * NK * NM * NI) { const float* t = x; x = Ws; Ws = t; }
    float* out = (float*)d_out;

    const int SMEM_U = BT * 128 * 12 * 4;                            // 98,304 B
    const int SMEM_R = (64 * UHR + 640 + 320) * 4;                   // 25,344 B
    cudaFuncSetAttribute(uhat_kernel,     cudaFuncAttributeMaxDynamicSharedMemorySize, SMEM_U);
    cudaFuncSetAttribute(route_kernel<0>, cudaFuncAttributeMaxDynamicSharedMemorySize, SMEM_R);
    cudaFuncSetAttribute(route_kernel<1>, cudaFuncAttributeMaxDynamicSharedMemorySize, SMEM_R);

    // 1) u_hat (fp16) + s0 partials
    uhat_kernel<<<dim3(9, 10, 8), 128, SMEM_U>>>(x, Ws);
    // 2..5) PDL-chained
    launch_pdl(route_kernel<0>,   dim3(36, 64), dim3(160), SMEM_R);
    launch_pdl(compute_w1_kernel, dim3(160),    dim3(256), 0);
    launch_pdl(route_kernel<1>,   dim3(36, 64), dim3(160), SMEM_R);
    launch_pdl(squash_final,      dim3(160),    dim3(256), 0, out);
}